// round 10
// baseline (speedup 1.0000x reference)
#include <cuda_runtime.h>
#include <cstdint>

#define S_LEN 512
#define BATCH 64
#define DIN   256
#define HID   1024
#define BH    (BATCH * HID)   // 65536

// ---------------------------------------------------------------------------
// packed f32x2 helpers (sm_100+ PTX)
// ---------------------------------------------------------------------------
__device__ __forceinline__ unsigned long long pack2(float x, float y) {
    unsigned long long u;
    asm("mov.b64 %0, {%1, %2};" : "=l"(u) : "f"(x), "f"(y));
    return u;
}
__device__ __forceinline__ void ffma2(unsigned long long &a,
                                      unsigned long long x,
                                      unsigned long long y) {
    asm("fma.rn.f32x2 %0, %1, %2, %0;" : "+l"(a) : "l"(x), "l"(y));
}
__device__ __forceinline__ float2 unpack2(unsigned long long u) {
    float x, y;
    asm("mov.b64 {%0, %1}, %2;" : "=f"(x), "=f"(y) : "l"(u));
    return make_float2(x, y);
}

// ---------------------------------------------------------------------------
// Phase 1: x_proj[s,b,h] = sum_k x[s,b,k] * W_in[h,k] + bias[h]
// GEMM M=32768, N=1024, K=256. Tile 64x64, 256 threads, 4x4 per thread,
// f32x2 packed FMAs. Writes directly into out[0 .. S*BH).
// ---------------------------------------------------------------------------
__global__ __launch_bounds__(256) void proj_kernel(
    const float* __restrict__ x,
    const float* __restrict__ Win,
    const float* __restrict__ bias,
    float* __restrict__ out)
{
    __shared__ float As[16][64];  // [k][m] transposed
    __shared__ float Bs[16][64];  // [k][n] transposed

    const int tid = threadIdx.x;
    const int n0  = blockIdx.x * 64;
    const int m0  = blockIdx.y * 64;
    const int tx  = tid & 15;       // n sub-tile
    const int ty  = tid >> 4;       // m sub-tile

    // loader mapping: one float4 per thread per tile
    const int lk4 = tid & 3;        // float4 index within 16-k chunk
    const int lr  = tid >> 2;       // row 0..63

    unsigned long long acc2[4][2];
#pragma unroll
    for (int i = 0; i < 4; i++) { acc2[i][0] = 0ull; acc2[i][1] = 0ull; }

    for (int k0 = 0; k0 < DIN; k0 += 16) {
        float4 a = *(const float4*)&x  [(m0 + lr) * DIN + k0 + lk4 * 4];
        float4 b = *(const float4*)&Win[(n0 + lr) * DIN + k0 + lk4 * 4];
        __syncthreads();
        As[lk4 * 4 + 0][lr] = a.x; As[lk4 * 4 + 1][lr] = a.y;
        As[lk4 * 4 + 2][lr] = a.z; As[lk4 * 4 + 3][lr] = a.w;
        Bs[lk4 * 4 + 0][lr] = b.x; Bs[lk4 * 4 + 1][lr] = b.y;
        Bs[lk4 * 4 + 2][lr] = b.z; Bs[lk4 * 4 + 3][lr] = b.w;
        __syncthreads();
#pragma unroll
        for (int k = 0; k < 16; k++) {
            float4 av = *(const float4*)&As[k][ty * 4];
            ulonglong2 bv = *(const ulonglong2*)&Bs[k][tx * 4];
            unsigned long long d0 = pack2(av.x, av.x);
            unsigned long long d1 = pack2(av.y, av.y);
            unsigned long long d2 = pack2(av.z, av.z);
            unsigned long long d3 = pack2(av.w, av.w);
            ffma2(acc2[0][0], d0, bv.x); ffma2(acc2[0][1], d0, bv.y);
            ffma2(acc2[1][0], d1, bv.x); ffma2(acc2[1][1], d1, bv.y);
            ffma2(acc2[2][0], d2, bv.x); ffma2(acc2[2][1], d2, bv.y);
            ffma2(acc2[3][0], d3, bv.x); ffma2(acc2[3][1], d3, bv.y);
        }
    }

    const float4 b4 = *(const float4*)&bias[n0 + tx * 4];
#pragma unroll
    for (int i = 0; i < 4; i++) {
        float2 p0 = unpack2(acc2[i][0]);
        float2 p1 = unpack2(acc2[i][1]);
        float4 v;
        v.x = p0.x + b4.x; v.y = p0.y + b4.y;
        v.z = p1.x + b4.z; v.w = p1.y + b4.w;
        *(float4*)&out[(m0 + ty * 4 + i) * HID + n0 + tx * 4] = v;
    }
}

// ---------------------------------------------------------------------------
// Global barrier for the persistent recurrence kernel.
// 128 CTAs, one per SM, all co-resident (grid <= 148, occ 1 guaranteed).
// Sense via monotonically increasing generation counter (graph-replay safe:
// count returns to 0, gen compared by equality only).
// ---------------------------------------------------------------------------
__device__ unsigned int g_count = 0;
__device__ unsigned int g_gen   = 0;

__device__ __forceinline__ void grid_barrier(unsigned int nb) {
    __threadfence();      // publish this thread's h stores device-wide
    __syncthreads();
    if (threadIdx.x == 0) {
        unsigned int gen = *(volatile unsigned int*)&g_gen;
        if (atomicAdd(&g_count, 1) == nb - 1) {
            atomicExch(&g_count, 0);
            __threadfence();
            atomicAdd(&g_gen, 1);
        } else {
            while (*(volatile unsigned int*)&g_gen == gen) { __nanosleep(64); }
        }
        __threadfence();
    }
    __syncthreads();
}

// ---------------------------------------------------------------------------
// Phase 2: persistent recurrence.
// 128 CTAs x 256 threads. CTA owns 8 output columns (W_hh rows) in smem.
// Warp w handles batch rows w*8 .. w*8+7, processed as 2 groups of 4 rows;
// each W LDS.128 is amortized over the 4 registered h rows (f32x2 MACs).
// h_prev for step t is out[t-1]; x_proj lives in out[t] and is overwritten
// in place by h_t. h_n written at t = S-1.
// ---------------------------------------------------------------------------
__global__ __launch_bounds__(256, 1) void rnn_kernel(
    const float* __restrict__ Whh,
    const float* __restrict__ alpha,
    float* __restrict__ out)
{
    __shared__ float sW[8 * HID];   // 32 KB: rows jbase..jbase+7 of W_hh
    __shared__ float sAl[8];

    const int tid   = threadIdx.x;
    const int lane  = tid & 31;
    const int wid   = tid >> 5;
    const int jbase = blockIdx.x * 8;
    const unsigned nb = gridDim.x;

    {   // stage W_hh slice (contiguous rows) and alpha
        const float4* src = (const float4*)(Whh + jbase * HID);
        float4* dst = (float4*)sW;
        for (int i = tid; i < (8 * HID) / 4; i += 256) dst[i] = src[i];
        if (tid < 8) sAl[tid] = alpha[jbase + tid];
    }
    __syncthreads();

    const int bbase = wid * 8;

#pragma unroll 1
    for (int t = 0; t < S_LEN; t++) {
        const float* hp = (t == 0) ? nullptr : (out + (t - 1) * BH);
        float* xo = out + t * BH;

#pragma unroll 1
        for (int g = 0; g < 2; g++) {
            const int b0 = bbase + g * 4;

            unsigned long long acc[4][8];
#pragma unroll
            for (int bb = 0; bb < 4; bb++)
#pragma unroll
                for (int j = 0; j < 8; j++) acc[bb][j] = 0ull;

#pragma unroll 1
            for (int half = 0; half < 2; half++) {
                // load half of h_prev rows b0..b0+3 into packed registers
                unsigned long long hlo[4][4], hhi[4][4];
#pragma unroll
                for (int bb = 0; bb < 4; bb++) {
                    if (hp != nullptr) {
                        const float4* hr = (const float4*)(hp + (b0 + bb) * HID);
#pragma unroll
                        for (int i = 0; i < 4; i++) {
                            float4 v = __ldcg(hr + (half * 4 + i) * 32 + lane);
                            hlo[bb][i] = pack2(v.x, v.y);
                            hhi[bb][i] = pack2(v.z, v.w);
                        }
                    } else {
#pragma unroll
                        for (int i = 0; i < 4; i++) { hlo[bb][i] = 0ull; hhi[bb][i] = 0ull; }
                    }
                }
#pragma unroll
                for (int j = 0; j < 8; j++) {
                    const ulonglong2* wr = (const ulonglong2*)(sW + j * HID);
#pragma unroll
                    for (int i = 0; i < 4; i++) {
                        ulonglong2 w = wr[(half * 4 + i) * 32 + lane];
#pragma unroll
                        for (int bb = 0; bb < 4; bb++) {
                            ffma2(acc[bb][j], hlo[bb][i], w.x);
                            ffma2(acc[bb][j], hhi[bb][i], w.y);
                        }
                    }
                }
            }

            // reduce 32 lane-partials per (b, j), apply tanh/mix, store
#pragma unroll
            for (int bb = 0; bb < 4; bb++) {
                const int b = b0 + bb;
#pragma unroll
                for (int j = 0; j < 8; j++) {
                    float2 p = unpack2(acc[bb][j]);
                    float s = p.x + p.y;
                    s += __shfl_xor_sync(0xffffffffu, s, 16);
                    s += __shfl_xor_sync(0xffffffffu, s, 8);
                    s += __shfl_xor_sync(0xffffffffu, s, 4);
                    s += __shfl_xor_sync(0xffffffffu, s, 2);
                    s += __shfl_xor_sync(0xffffffffu, s, 1);
                    if (lane == j) {
                        const int jg = jbase + j;
                        float xp = __ldcg(xo + b * HID + jg);          // x_proj (in place)
                        float hprev = (hp != nullptr) ? __ldcg(hp + b * HID + jg) : 0.0f;
                        float a = sAl[j];
                        float ht = (1.0f - a) * hprev + a * tanhf(xp + s);
                        xo[b * HID + jg] = ht;                          // output[t]
                        if (t == S_LEN - 1)
                            out[S_LEN * BH + b * HID + jg] = ht;        // h_n
                    }
                }
            }
        }
        grid_barrier(nb);
    }
}

// ---------------------------------------------------------------------------
// launch
// inputs (metadata order): x [S,B,DIN], W_in [H,DIN], W_hh [H,H],
//                          bias [H], alpha [H]
// out: [S,B,H] output followed by [B,H] h_n (fp32)
// ---------------------------------------------------------------------------
extern "C" void kernel_launch(void* const* d_in, const int* in_sizes, int n_in,
                              void* d_out, int out_size) {
    const float* x     = (const float*)d_in[0];
    const float* Win   = (const float*)d_in[1];
    const float* Whh   = (const float*)d_in[2];
    const float* bias  = (const float*)d_in[3];
    const float* alpha = (const float*)d_in[4];
    float* out = (float*)d_out;

    dim3 g1(HID / 64, (S_LEN * BATCH) / 64);   // (16, 512)
    proj_kernel<<<g1, 256>>>(x, Win, bias, out);
    rnn_kernel<<<128, 256>>>(Whh, alpha, out);
}

// round 16
// speedup vs baseline: 4.7345x; 4.7345x over previous
#include <cuda_runtime.h>
#include <cstdint>

#define S_LEN 512
#define BATCH 64
#define DIN   256
#define HID   1024
#define BH    (BATCH * HID)   // 65536

// ---------------------------------------------------------------------------
// packed f32x2 helpers (sm_100+ PTX)
// ---------------------------------------------------------------------------
__device__ __forceinline__ unsigned long long pack2(float x, float y) {
    unsigned long long u;
    asm("mov.b64 %0, {%1, %2};" : "=l"(u) : "f"(x), "f"(y));
    return u;
}
__device__ __forceinline__ void ffma2(unsigned long long &a,
                                      unsigned long long x,
                                      unsigned long long y) {
    asm("fma.rn.f32x2 %0, %1, %2, %0;" : "+l"(a) : "l"(x), "l"(y));
}
__device__ __forceinline__ float2 unpack2(unsigned long long u) {
    float x, y;
    asm("mov.b64 {%0, %1}, %2;" : "=f"(x), "=f"(y) : "l"(u));
    return make_float2(x, y);
}

// ---------------------------------------------------------------------------
// Phase 1: x_proj[s,b,h] = sum_k x[s,b,k] * W_in[h,k] + bias[h]
// GEMM M=32768, N=1024, K=256. Tile 64x64, 256 threads, 4x4 per thread,
// f32x2 packed FMAs. Writes directly into out[0 .. S*BH).
// ---------------------------------------------------------------------------
__global__ __launch_bounds__(256) void proj_kernel(
    const float* __restrict__ x,
    const float* __restrict__ Win,
    const float* __restrict__ bias,
    float* __restrict__ out)
{
    __shared__ float As[16][64];  // [k][m] transposed
    __shared__ float Bs[16][64];  // [k][n] transposed

    const int tid = threadIdx.x;
    const int n0  = blockIdx.x * 64;
    const int m0  = blockIdx.y * 64;
    const int tx  = tid & 15;       // n sub-tile
    const int ty  = tid >> 4;       // m sub-tile

    const int lk4 = tid & 3;        // float4 index within 16-k chunk
    const int lr  = tid >> 2;       // row 0..63

    unsigned long long acc2[4][2];
#pragma unroll
    for (int i = 0; i < 4; i++) { acc2[i][0] = 0ull; acc2[i][1] = 0ull; }

    for (int k0 = 0; k0 < DIN; k0 += 16) {
        float4 a = *(const float4*)&x  [(m0 + lr) * DIN + k0 + lk4 * 4];
        float4 b = *(const float4*)&Win[(n0 + lr) * DIN + k0 + lk4 * 4];
        __syncthreads();
        As[lk4 * 4 + 0][lr] = a.x; As[lk4 * 4 + 1][lr] = a.y;
        As[lk4 * 4 + 2][lr] = a.z; As[lk4 * 4 + 3][lr] = a.w;
        Bs[lk4 * 4 + 0][lr] = b.x; Bs[lk4 * 4 + 1][lr] = b.y;
        Bs[lk4 * 4 + 2][lr] = b.z; Bs[lk4 * 4 + 3][lr] = b.w;
        __syncthreads();
#pragma unroll
        for (int k = 0; k < 16; k++) {
            float4 av = *(const float4*)&As[k][ty * 4];
            ulonglong2 bv = *(const ulonglong2*)&Bs[k][tx * 4];
            unsigned long long d0 = pack2(av.x, av.x);
            unsigned long long d1 = pack2(av.y, av.y);
            unsigned long long d2 = pack2(av.z, av.z);
            unsigned long long d3 = pack2(av.w, av.w);
            ffma2(acc2[0][0], d0, bv.x); ffma2(acc2[0][1], d0, bv.y);
            ffma2(acc2[1][0], d1, bv.x); ffma2(acc2[1][1], d1, bv.y);
            ffma2(acc2[2][0], d2, bv.x); ffma2(acc2[2][1], d2, bv.y);
            ffma2(acc2[3][0], d3, bv.x); ffma2(acc2[3][1], d3, bv.y);
        }
    }

    const float4 b4 = *(const float4*)&bias[n0 + tx * 4];
#pragma unroll
    for (int i = 0; i < 4; i++) {
        float2 p0 = unpack2(acc2[i][0]);
        float2 p1 = unpack2(acc2[i][1]);
        float4 v;
        v.x = p0.x + b4.x; v.y = p0.y + b4.y;
        v.z = p1.x + b4.z; v.w = p1.y + b4.w;
        *(float4*)&out[(m0 + ty * 4 + i) * HID + n0 + tx * 4] = v;
    }
}

// ---------------------------------------------------------------------------
// Global barrier: 128 co-resident CTAs (one per SM, grid <= SM count,
// 512 thr/CTA -> occupancy 1 guaranteed, so the barrier cannot deadlock).
// Generation counter (graph-replay safe: only equality compares on gen).
// Fast path: tight poll; after a bounded number of misses, yield with
// nanosleep so a straggler never looks like a hang.
// ---------------------------------------------------------------------------
__device__ unsigned int g_count = 0;
__device__ unsigned int g_gen   = 0;

__device__ __forceinline__ void grid_barrier(unsigned int nb) {
    __threadfence();      // publish this thread's h stores device-wide
    __syncthreads();
    if (threadIdx.x == 0) {
        unsigned int gen = *(volatile unsigned int*)&g_gen;
        if (atomicAdd(&g_count, 1) == nb - 1) {
            atomicExch(&g_count, 0);
            __threadfence();
            atomicAdd(&g_gen, 1);
        } else {
            int spins = 0;
            while (*(volatile unsigned int*)&g_gen == gen) {
                if (++spins > 4096) __nanosleep(64);
            }
        }
        __threadfence();
    }
    __syncthreads();
}

// ---------------------------------------------------------------------------
// Phase 2: persistent recurrence. 128 CTAs x 512 threads (16 warps).
// CTA owns 8 output columns (rows of W_hh) staged in smem (32 KB).
// Warp w owns batch rows w*4 .. w*4+3. k processed in 8 chunks of 128 with
// double-buffered __ldcg prefetch of the next h chunk during FFMA of the
// current one. Each W LDS.128 amortized over 4 batch rows (f32x2 MACs).
// Tail: xp/hprev scalars prefetched at step start (hidden behind GEMM);
// butterfly reduce leaves exactly one output per lane -> one coalesced STG
// per warp. h_prev for step t is out[t-1]; x_proj lives in out[t] and is
// overwritten in place by h_t. h_n written at t = S-1 (no trailing barrier).
// ---------------------------------------------------------------------------
__global__ __launch_bounds__(512, 1) void rnn_kernel(
    const float* __restrict__ Whh,
    const float* __restrict__ alpha,
    float* __restrict__ out)
{
    __shared__ float sW[8 * HID];   // 32 KB: rows jbase..jbase+7 of W_hh
    __shared__ float sAl[8];

    const int tid   = threadIdx.x;
    const int lane  = tid & 31;
    const int wid   = tid >> 5;
    const int jbase = blockIdx.x * 8;
    const unsigned nb = gridDim.x;

    {   // stage W_hh slice (contiguous rows) and alpha
        const float4* src = (const float4*)(Whh + jbase * HID);
        float4* dst = (float4*)sW;
        for (int i = tid; i < (8 * HID) / 4; i += 512) dst[i] = src[i];
        if (tid < 8) sAl[tid] = alpha[tid + jbase];
    }
    __syncthreads();

    const int b0     = wid * 4;
    const int my_bb  = lane >> 3;            // 0..3
    const int my_j   = lane & 7;             // 0..7
    const int my_off = (b0 + my_bb) * HID + (jbase + my_j);
    const float my_a = sAl[my_j];

#pragma unroll 1
    for (int t = 0; t < S_LEN; t++) {
        float* xo = out + t * BH;

        // prefetch tail operands first (L2 latency hidden by the GEMM body)
        float xp_s = __ldcg(xo + my_off);
        float hp_s = 0.0f;
        float myval = 0.0f;

        if (t > 0) {
            const float* hp = out + (t - 1) * BH;
            hp_s = __ldcg(hp + my_off);

            // row pointers: lane covers 16B (4 k-values) per 128-k chunk
            const ulonglong2* hrow[4];
#pragma unroll
            for (int bb = 0; bb < 4; bb++)
                hrow[bb] = (const ulonglong2*)(hp + (b0 + bb) * HID) + lane;

            ulonglong2 hbuf[2][4];
#pragma unroll
            for (int bb = 0; bb < 4; bb++) hbuf[0][bb] = __ldcg(hrow[bb]);

            unsigned long long acc[4][8];
#pragma unroll
            for (int bb = 0; bb < 4; bb++)
#pragma unroll
                for (int j = 0; j < 8; j++) acc[bb][j] = 0ull;

#pragma unroll
            for (int c = 0; c < 8; c++) {
                if (c < 7) {
#pragma unroll
                    for (int bb = 0; bb < 4; bb++)
                        hbuf[(c + 1) & 1][bb] = __ldcg(hrow[bb] + (c + 1) * 32);
                }
                const float* wbase = sW + c * 128 + lane * 4;
#pragma unroll
                for (int j = 0; j < 8; j++) {
                    ulonglong2 w = *(const ulonglong2*)(wbase + j * HID);
#pragma unroll
                    for (int bb = 0; bb < 4; bb++) {
                        ffma2(acc[bb][j], hbuf[c & 1][bb].x, w.x);
                        ffma2(acc[bb][j], hbuf[c & 1][bb].y, w.y);
                    }
                }
            }

            // butterfly reduce 32 lane-partials per (bb,j);
            // lane bb*8+j keeps its own output
#pragma unroll
            for (int bb = 0; bb < 4; bb++) {
#pragma unroll
                for (int j = 0; j < 8; j++) {
                    float2 p = unpack2(acc[bb][j]);
                    float s = p.x + p.y;
                    s += __shfl_xor_sync(0xffffffffu, s, 16);
                    s += __shfl_xor_sync(0xffffffffu, s, 8);
                    s += __shfl_xor_sync(0xffffffffu, s, 4);
                    s += __shfl_xor_sync(0xffffffffu, s, 2);
                    s += __shfl_xor_sync(0xffffffffu, s, 1);
                    if (lane == bb * 8 + j) myval = s;
                }
            }
        }

        // every lane owns exactly one (b, j) output -> coalesced stores
        float ht = (1.0f - my_a) * hp_s + my_a * tanhf(xp_s + myval);
        xo[my_off] = ht;                                  // output[t]
        if (t == S_LEN - 1) {
            out[S_LEN * BH + my_off] = ht;                // h_n
        } else {
            grid_barrier(nb);
        }
    }
}

// ---------------------------------------------------------------------------
// launch
// inputs (metadata order): x [S,B,DIN], W_in [H,DIN], W_hh [H,H],
//                          bias [H], alpha [H]
// out: [S,B,H] output followed by [B,H] h_n (fp32)
// ---------------------------------------------------------------------------
extern "C" void kernel_launch(void* const* d_in, const int* in_sizes, int n_in,
                              void* d_out, int out_size) {
    const float* x     = (const float*)d_in[0];
    const float* Win   = (const float*)d_in[1];
    const float* Whh   = (const float*)d_in[2];
    const float* bias  = (const float*)d_in[3];
    const float* alpha = (const float*)d_in[4];
    float* out = (float*)d_out;

    dim3 g1(HID / 64, (S_LEN * BATCH) / 64);   // (16, 512)
    proj_kernel<<<g1, 256>>>(x, Win, bias, out);
    rnn_kernel<<<128, 512>>>(Whh, alpha, out);
}

// round 17
// speedup vs baseline: 5.6471x; 1.1928x over previous
#include <cuda_runtime.h>
#include <cstdint>

#define S_LEN 512
#define BATCH 64
#define DIN   256
#define HID   1024
#define BH    (BATCH * HID)   // 65536

// ---------------------------------------------------------------------------
// packed f32x2 helpers (sm_100+ PTX)
// ---------------------------------------------------------------------------
__device__ __forceinline__ unsigned long long pack2(float x, float y) {
    unsigned long long u;
    asm("mov.b64 %0, {%1, %2};" : "=l"(u) : "f"(x), "f"(y));
    return u;
}
__device__ __forceinline__ void ffma2(unsigned long long &a,
                                      unsigned long long x,
                                      unsigned long long y) {
    asm("fma.rn.f32x2 %0, %1, %2, %0;" : "+l"(a) : "l"(x), "l"(y));
}
__device__ __forceinline__ float2 unpack2(unsigned long long u) {
    float x, y;
    asm("mov.b64 {%0, %1}, %2;" : "=f"(x), "=f"(y) : "l"(u));
    return make_float2(x, y);
}

// ---------------------------------------------------------------------------
// Phase 1: x_proj[s,b,h] = sum_k x[s,b,k] * W_in[h,k] + bias[h]
// GEMM M=32768, N=1024, K=256. Tile 64x64, 256 threads, 4x4 per thread.
// ---------------------------------------------------------------------------
__global__ __launch_bounds__(256) void proj_kernel(
    const float* __restrict__ x,
    const float* __restrict__ Win,
    const float* __restrict__ bias,
    float* __restrict__ out)
{
    __shared__ float As[16][64];  // [k][m]
    __shared__ float Bs[16][64];  // [k][n]

    const int tid = threadIdx.x;
    const int n0  = blockIdx.x * 64;
    const int m0  = blockIdx.y * 64;
    const int tx  = tid & 15;
    const int ty  = tid >> 4;

    const int lk4 = tid & 3;
    const int lr  = tid >> 2;

    unsigned long long acc2[4][2];
#pragma unroll
    for (int i = 0; i < 4; i++) { acc2[i][0] = 0ull; acc2[i][1] = 0ull; }

    for (int k0 = 0; k0 < DIN; k0 += 16) {
        float4 a = *(const float4*)&x  [(m0 + lr) * DIN + k0 + lk4 * 4];
        float4 b = *(const float4*)&Win[(n0 + lr) * DIN + k0 + lk4 * 4];
        __syncthreads();
        As[lk4 * 4 + 0][lr] = a.x; As[lk4 * 4 + 1][lr] = a.y;
        As[lk4 * 4 + 2][lr] = a.z; As[lk4 * 4 + 3][lr] = a.w;
        Bs[lk4 * 4 + 0][lr] = b.x; Bs[lk4 * 4 + 1][lr] = b.y;
        Bs[lk4 * 4 + 2][lr] = b.z; Bs[lk4 * 4 + 3][lr] = b.w;
        __syncthreads();
#pragma unroll
        for (int k = 0; k < 16; k++) {
            float4 av = *(const float4*)&As[k][ty * 4];
            ulonglong2 bv = *(const ulonglong2*)&Bs[k][tx * 4];
            unsigned long long d0 = pack2(av.x, av.x);
            unsigned long long d1 = pack2(av.y, av.y);
            unsigned long long d2 = pack2(av.z, av.z);
            unsigned long long d3 = pack2(av.w, av.w);
            ffma2(acc2[0][0], d0, bv.x); ffma2(acc2[0][1], d0, bv.y);
            ffma2(acc2[1][0], d1, bv.x); ffma2(acc2[1][1], d1, bv.y);
            ffma2(acc2[2][0], d2, bv.x); ffma2(acc2[2][1], d2, bv.y);
            ffma2(acc2[3][0], d3, bv.x); ffma2(acc2[3][1], d3, bv.y);
        }
    }

    const float4 b4 = *(const float4*)&bias[n0 + tx * 4];
#pragma unroll
    for (int i = 0; i < 4; i++) {
        float2 p0 = unpack2(acc2[i][0]);
        float2 p1 = unpack2(acc2[i][1]);
        float4 v;
        v.x = p0.x + b4.x; v.y = p0.y + b4.y;
        v.z = p1.x + b4.z; v.w = p1.y + b4.w;
        *(float4*)&out[(m0 + ty * 4 + i) * HID + n0 + tx * 4] = v;
    }
}

// ---------------------------------------------------------------------------
// Flag-array grid barrier. 128 co-resident CTAs (one per SM; 512 thr -> occ 1).
// Monotonic counters (persist across graph replays; no reset needed):
//   slot[cta] = number of barriers this CTA has EVER passed
//   g_gen     = number of barriers released
// target for barrier t within a launch = base + t + 1, base = g_gen at entry.
// Arrival: 128 parallel st.release (4 L2 lines, no atomic serialization).
// CTA0 warp0 gathers all 128 slots with 32 lane-parallel ld.v4.
// ---------------------------------------------------------------------------
__device__ __align__(16) unsigned int g_arrive[128];
__device__ unsigned int g_gen;

__device__ __forceinline__ void grid_barrier(unsigned target, int cta, int tid) {
    __syncthreads();   // all threads' h stores done (program order)
    if (tid == 0) {
        asm volatile("st.release.gpu.global.u32 [%0], %1;"
                     :: "l"(&g_arrive[cta]), "r"(target) : "memory");
    }
    if (cta == 0) {
        if (tid < 32) {
            const unsigned int* p = g_arrive + tid * 4;
            for (;;) {
                unsigned a0, a1, a2, a3;
                asm volatile("ld.relaxed.gpu.global.v4.u32 {%0,%1,%2,%3}, [%4];"
                             : "=r"(a0), "=r"(a1), "=r"(a2), "=r"(a3)
                             : "l"(p) : "memory");
                bool ok = ((int)(a0 - target) >= 0) & ((int)(a1 - target) >= 0) &
                          ((int)(a2 - target) >= 0) & ((int)(a3 - target) >= 0);
                if (__all_sync(0xffffffffu, ok)) break;
            }
            asm volatile("fence.acq_rel.gpu;" ::: "memory");
            if (tid == 0) {
                asm volatile("st.relaxed.gpu.global.u32 [%0], %1;"
                             :: "l"(&g_gen), "r"(target) : "memory");
            }
        }
    } else {
        if (tid == 0) {
            unsigned g;
            do {
                asm volatile("ld.acquire.gpu.global.u32 %0, [%1];"
                             : "=r"(g) : "l"(&g_gen) : "memory");
            } while ((int)(g - target) < 0);
        }
    }
    __syncthreads();
}

// ---------------------------------------------------------------------------
// Phase 2: persistent recurrence. 128 CTAs x 512 threads (16 warps).
// CTA owns 8 output columns (rows of W_hh) in smem. Warp w owns batch rows
// w*4..w*4+3. k in 8 chunks of 128, double-buffered __ldcg h prefetch, each
// W LDS.128 amortized over 4 batch rows (f32x2 MACs).
// Tail: butterfly transpose-reduce (31 shfls, first stage fused with acc
// unpack); lane L ends holding exactly the output for (b,j) = (L>>3, L&7).
// hp scalar carried in a register across steps; next xp prefetched at step
// top (out[t+1] holds x_proj, stable until step t+1). One coalesced STG/warp.
// ---------------------------------------------------------------------------
__global__ __launch_bounds__(512, 1) void rnn_kernel(
    const float* __restrict__ Whh,
    const float* __restrict__ alpha,
    float* __restrict__ out)
{
    __shared__ float sW[8 * HID];   // 32 KB
    __shared__ float sAl[8];

    const int tid   = threadIdx.x;
    const int lane  = tid & 31;
    const int wid   = tid >> 5;
    const int cta   = blockIdx.x;
    const int jbase = cta * 8;

    unsigned gen_base;
    asm volatile("ld.relaxed.gpu.global.u32 %0, [%1];"
                 : "=r"(gen_base) : "l"(&g_gen) : "memory");

    {   // stage W_hh slice and alpha
        const float4* src = (const float4*)(Whh + jbase * HID);
        float4* dst = (float4*)sW;
        for (int i = tid; i < (8 * HID) / 4; i += 512) dst[i] = src[i];
        if (tid < 8) sAl[tid] = alpha[tid + jbase];
    }
    __syncthreads();

    const int b0     = wid * 4;
    const int my_bb  = lane >> 3;            // 0..3
    const int my_j   = lane & 7;             // 0..7
    const int my_off = (b0 + my_bb) * HID + (jbase + my_j);
    const float my_a = sAl[my_j];

    float xp_cur = __ldcg(out + my_off);     // x_proj[0] at my element
    float h_my   = 0.0f;                     // my h_prev element (register)

#pragma unroll 1
    for (int t = 0; t < S_LEN; t++) {
        float* xo = out + t * BH;

        // prefetch NEXT step's x_proj early (out[t+1] untouched until t+1)
        float xp_next = 0.0f;
        if (t + 1 < S_LEN) xp_next = __ldcg(out + (t + 1) * BH + my_off);

        float myval = 0.0f;

        if (t > 0) {
            const float* hp = out + (t - 1) * BH;

            const ulonglong2* hrow[4];
#pragma unroll
            for (int bb = 0; bb < 4; bb++)
                hrow[bb] = (const ulonglong2*)(hp + (b0 + bb) * HID) + lane;

            ulonglong2 hbuf[2][4];
#pragma unroll
            for (int bb = 0; bb < 4; bb++) hbuf[0][bb] = __ldcg(hrow[bb]);

            unsigned long long acc[4][8];
#pragma unroll
            for (int bb = 0; bb < 4; bb++)
#pragma unroll
                for (int j = 0; j < 8; j++) acc[bb][j] = 0ull;

#pragma unroll
            for (int c = 0; c < 8; c++) {
                if (c < 7) {
#pragma unroll
                    for (int bb = 0; bb < 4; bb++)
                        hbuf[(c + 1) & 1][bb] = __ldcg(hrow[bb] + (c + 1) * 32);
                }
                const float* wbase = sW + c * 128 + lane * 4;
#pragma unroll
                for (int j = 0; j < 8; j++) {
                    ulonglong2 w = *(const ulonglong2*)(wbase + j * HID);
#pragma unroll
                    for (int bb = 0; bb < 4; bb++) {
                        ffma2(acc[bb][j], hbuf[c & 1][bb].x, w.x);
                        ffma2(acc[bb][j], hbuf[c & 1][bb].y, w.y);
                    }
                }
            }

            // butterfly transpose-reduce: 31 shfls, lane L ends with its own
            // (b,j) sum in v[0]. Stage o=16 fused with acc unpack (keeps
            // register peak low: acc dies as v is built).
            float v[16];
#pragma unroll
            for (int i = 0; i < 16; i++) {
                float2 pa = unpack2(acc[i >> 3][i & 7]);        // dest i
                float2 pb = unpack2(acc[2 + (i >> 3)][i & 7]);  // dest i+16
                float a0 = pa.x + pa.y;
                float b0v = pb.x + pb.y;
                float send = (lane & 16) ? a0 : b0v;
                float recv = __shfl_xor_sync(0xffffffffu, send, 16);
                v[i] = ((lane & 16) ? b0v : a0) + recv;
            }
#pragma unroll
            for (int i = 0; i < 8; i++) {
                float send = (lane & 8) ? v[i] : v[i + 8];
                float recv = __shfl_xor_sync(0xffffffffu, send, 8);
                v[i] = ((lane & 8) ? v[i + 8] : v[i]) + recv;
            }
#pragma unroll
            for (int i = 0; i < 4; i++) {
                float send = (lane & 4) ? v[i] : v[i + 4];
                float recv = __shfl_xor_sync(0xffffffffu, send, 4);
                v[i] = ((lane & 4) ? v[i + 4] : v[i]) + recv;
            }
#pragma unroll
            for (int i = 0; i < 2; i++) {
                float send = (lane & 2) ? v[i] : v[i + 2];
                float recv = __shfl_xor_sync(0xffffffffu, send, 2);
                v[i] = ((lane & 2) ? v[i + 2] : v[i]) + recv;
            }
            {
                float send = (lane & 1) ? v[0] : v[1];
                float recv = __shfl_xor_sync(0xffffffffu, send, 1);
                v[0] = ((lane & 1) ? v[1] : v[0]) + recv;
            }
            myval = v[0];
        }

        float ht = (1.0f - my_a) * h_my + my_a * tanhf(xp_cur + myval);
        xo[my_off] = ht;            // output[t] (coalesced per warp)
        h_my = ht;

        if (t == S_LEN - 1) {
            out[S_LEN * BH + my_off] = ht;   // h_n
        } else {
            grid_barrier(gen_base + (unsigned)t + 1u, cta, tid);
        }
        xp_cur = xp_next;
    }
}

// ---------------------------------------------------------------------------
// launch
// inputs: x [S,B,DIN], W_in [H,DIN], W_hh [H,H], bias [H], alpha [H]
// out: [S,B,H] output followed by [B,H] h_n (fp32)
// ---------------------------------------------------------------------------
extern "C" void kernel_launch(void* const* d_in, const int* in_sizes, int n_in,
                              void* d_out, int out_size) {
    const float* x     = (const float*)d_in[0];
    const float* Win   = (const float*)d_in[1];
    const float* Whh   = (const float*)d_in[2];
    const float* bias  = (const float*)d_in[3];
    const float* alpha = (const float*)d_in[4];
    float* out = (float*)d_out;

    dim3 g1(HID / 64, (S_LEN * BATCH) / 64);   // (16, 512)
    proj_kernel<<<g1, 256>>>(x, Win, bias, out);
    rnn_kernel<<<128, 512>>>(Whh, alpha, out);
}